// round 5
// baseline (speedup 1.0000x reference)
#include <cuda_runtime.h>
#include <cuda_bf16.h>
#include <cstdint>

// Problem constants
#define BATCH 16
#define CIN   384
#define HH    56
#define WW    56
#define PIX   (HH*WW)          // 3136
#define COUT  384
#define KDIM  768              // 2*CIN
#define BN_EPS 1e-5f

// GEMM tile config
#define BM 128
#define BNT 128
#define BK 32
#define ASTRIDE 40             // padded bf16 stride for A smem (16B-aligned rows, conflict-free frag loads)
#define BSTRIDE 136            // padded bf16 stride for B smem

// -------- scratch (static device globals; no allocation allowed) --------
__device__ __nv_bfloat16 g_XH[(size_t)BATCH * KDIM * PIX];   // 77 MB
__device__ __nv_bfloat16 g_XL[(size_t)BATCH * KDIM * PIX];   // 77 MB
__device__ __nv_bfloat16 g_WH[COUT * KDIM];
__device__ __nv_bfloat16 g_WL[COUT * KDIM];
__device__ float         g_TB[COUT];

// -------------------- kernel 1: weight prep (fold BN, split bf16) --------------------
__global__ void wprep_kernel(const float* __restrict__ w, const float* __restrict__ cb,
                             const float* __restrict__ sc, const float* __restrict__ bi,
                             const float* __restrict__ mu, const float* __restrict__ var) {
    int i = blockIdx.x * 256 + threadIdx.x;
    if (i < COUT * KDIM) {
        int o = i / KDIM;
        float s = sc[o] * rsqrtf(var[o] + BN_EPS);
        float wv = w[i] * s;
        __nv_bfloat16 h = __float2bfloat16(wv);
        g_WH[i] = h;
        g_WL[i] = __float2bfloat16(wv - __bfloat162float(h));
    }
    if (i < COUT) {
        float s = sc[i] * rsqrtf(var[i] + BN_EPS);
        g_TB[i] = (cb[i] - mu[i]) * s + bi[i];
    }
}

// -------------------- kernel 2: shift-max + bf16 hi/lo split writer --------------------
// One block per (b,c) plane. Plane lives in smem; compute x_j with circular shifts.
__global__ __launch_bounds__(256) void shift_split_kernel(const float* __restrict__ x) {
    const int bc = blockIdx.x;           // b*CIN + c
    const int c  = bc % CIN;
    const int b  = bc / CIN;
    __shared__ float pl[PIX];
    const float* src = x + (size_t)bc * PIX;
    for (int i = threadIdx.x; i < PIX; i += 256) pl[i] = src[i];
    __syncthreads();

    const size_t baseX = ((size_t)b * KDIM + c)       * PIX;
    const size_t baseJ = ((size_t)b * KDIM + CIN + c) * PIX;

    for (int i = threadIdx.x; i < PIX; i += 256) {
        int h = i / WW, w = i % WW;
        float v = pl[i];
        float m = 0.0f;
        const int shifts[5] = {1, 3, 7, 15, 31};
        #pragma unroll
        for (int j = 0; j < 5; j++) {
            int s = shifts[j];
            int hm = h - s; if (hm < 0)   hm += HH;
            int hp = h + s; if (hp >= HH) hp -= HH;
            m = fmaxf(m, v - pl[hm * WW + w]);
            m = fmaxf(m, v - pl[hp * WW + w]);
            int wm = w - s; if (wm < 0)   wm += WW;
            int wp = w + s; if (wp >= WW) wp -= WW;
            m = fmaxf(m, v - pl[h * WW + wm]);
            m = fmaxf(m, v - pl[h * WW + wp]);
        }
        __nv_bfloat16 xh = __float2bfloat16(v);
        g_XH[baseX + i] = xh;
        g_XL[baseX + i] = __float2bfloat16(v - __bfloat162float(xh));
        __nv_bfloat16 jh = __float2bfloat16(m);
        g_XH[baseJ + i] = jh;
        g_XL[baseJ + i] = __float2bfloat16(m - __bfloat162float(jh));
    }
}

// -------------------- kernel 3: GEMM (bf16 3-term split) + BN-folded bias + exact GELU --------------------
__device__ __forceinline__ uint32_t pk2(const __nv_bfloat16* lo, const __nv_bfloat16* hi) {
    uint32_t a = *(const unsigned short*)lo;
    uint32_t b = *(const unsigned short*)hi;
    return a | (b << 16);
}

__device__ __forceinline__ void mma16816(float* c, uint32_t a0, uint32_t a1, uint32_t a2, uint32_t a3,
                                         uint32_t b0, uint32_t b1) {
    asm volatile(
        "mma.sync.aligned.m16n8k16.row.col.f32.bf16.bf16.f32 "
        "{%0,%1,%2,%3}, {%4,%5,%6,%7}, {%8,%9}, {%0,%1,%2,%3};\n"
        : "+f"(c[0]), "+f"(c[1]), "+f"(c[2]), "+f"(c[3])
        : "r"(a0), "r"(a1), "r"(a2), "r"(a3), "r"(b0), "r"(b1));
}

__device__ __forceinline__ float gelu_exact(float v) {
    return 0.5f * v * (1.0f + erff(v * 0.7071067811865476f));
}

__global__ __launch_bounds__(256) void gemm_kernel(float* __restrict__ out) {
    const int pt = blockIdx.x;    // pixel tile (25)
    const int mt = blockIdx.y;    // cout tile (3)
    const int b  = blockIdx.z;    // batch (16)
    const int p0 = pt * BNT;
    const int o0 = mt * BM;
    const int tid  = threadIdx.x;
    const int lane = tid & 31;
    const int warp = tid >> 5;
    const int wm = warp >> 2;     // 0..1 -> m offset *64
    const int wn = warp & 3;      // 0..3 -> n offset *32

    __shared__ __nv_bfloat16 As[BM * ASTRIDE];
    __shared__ __nv_bfloat16 Bs[BK * BSTRIDE];

    float acc[4][4][4];
    #pragma unroll
    for (int i = 0; i < 4; i++)
        #pragma unroll
        for (int j = 0; j < 4; j++)
            #pragma unroll
            for (int k = 0; k < 4; k++) acc[i][j][k] = 0.0f;

    const __nv_bfloat16* Apts[3] = {g_WH, g_WL, g_WH};
    const __nv_bfloat16* Bpts[3] = {g_XH, g_XH, g_XL};

    const int r_a  = lane >> 2;
    const int c_a  = (lane & 3) * 2;

    for (int t = 0; t < 3; t++) {
        const __nv_bfloat16* A  = Apts[t];
        const __nv_bfloat16* Bp = Bpts[t] + (size_t)b * KDIM * PIX;

        for (int kk = 0; kk < KDIM; kk += BK) {
            __syncthreads();   // previous compute done before overwriting smem
            // load A tile: 128 x 32 bf16 (512 uint4)
            #pragma unroll
            for (int i = 0; i < 2; i++) {
                int u = tid + i * 256;
                int r = u >> 2, sg = u & 3;
                *(uint4*)(As + r * ASTRIDE + sg * 8) =
                    *(const uint4*)(A + (size_t)(o0 + r) * KDIM + kk + sg * 8);
            }
            // load B tile: 32 x 128 bf16 (512 uint4), predicated on pixel bound
            #pragma unroll
            for (int i = 0; i < 2; i++) {
                int u = tid + i * 256;
                int k = u >> 4, sg = u & 15;
                int p = p0 + sg * 8;
                uint4 v = make_uint4(0u, 0u, 0u, 0u);
                if (p < PIX)
                    v = *(const uint4*)(Bp + (size_t)(kk + k) * PIX + p);
                *(uint4*)(Bs + k * BSTRIDE + sg * 8) = v;
            }
            __syncthreads();

            #pragma unroll
            for (int ks = 0; ks < BK; ks += 16) {
                // B fragments for this warp's 4 n-frags
                uint32_t bf[4][2];
                #pragma unroll
                for (int nf = 0; nf < 4; nf++) {
                    int bn = wn * 32 + nf * 8 + (lane >> 2);
                    int k0 = ks + (lane & 3) * 2;
                    bf[nf][0] = pk2(&Bs[k0 * BSTRIDE + bn],       &Bs[(k0 + 1) * BSTRIDE + bn]);
                    bf[nf][1] = pk2(&Bs[(k0 + 8) * BSTRIDE + bn], &Bs[(k0 + 9) * BSTRIDE + bn]);
                }
                #pragma unroll
                for (int mf = 0; mf < 4; mf++) {
                    int am = wm * 64 + mf * 16;
                    uint32_t a0 = *(const uint32_t*)&As[(am + r_a)     * ASTRIDE + ks + c_a];
                    uint32_t a1 = *(const uint32_t*)&As[(am + r_a + 8) * ASTRIDE + ks + c_a];
                    uint32_t a2 = *(const uint32_t*)&As[(am + r_a)     * ASTRIDE + ks + c_a + 8];
                    uint32_t a3 = *(const uint32_t*)&As[(am + r_a + 8) * ASTRIDE + ks + c_a + 8];
                    #pragma unroll
                    for (int nf = 0; nf < 4; nf++)
                        mma16816(acc[mf][nf], a0, a1, a2, a3, bf[nf][0], bf[nf][1]);
                }
            }
        }
    }

    // epilogue: bias (BN folded) + exact GELU, write [b, o, p]
    float* outb = out + (size_t)b * COUT * PIX;
    #pragma unroll
    for (int mf = 0; mf < 4; mf++) {
        int r0 = o0 + wm * 64 + mf * 16 + (lane >> 2);
        float tb0 = g_TB[r0];
        float tb1 = g_TB[r0 + 8];
        #pragma unroll
        for (int nf = 0; nf < 4; nf++) {
            int p = p0 + wn * 32 + nf * 8 + (lane & 3) * 2;
            if (p < PIX) {
                float* o_lo = outb + (size_t)r0 * PIX + p;
                float* o_hi = outb + (size_t)(r0 + 8) * PIX + p;
                o_lo[0] = gelu_exact(acc[mf][nf][0] + tb0);
                o_lo[1] = gelu_exact(acc[mf][nf][1] + tb0);
                o_hi[0] = gelu_exact(acc[mf][nf][2] + tb1);
                o_hi[1] = gelu_exact(acc[mf][nf][3] + tb1);
            }
        }
    }
}

// -------------------- launch --------------------
extern "C" void kernel_launch(void* const* d_in, const int* in_sizes, int n_in,
                              void* d_out, int out_size) {
    const float* x      = (const float*)d_in[0];
    const float* conv_w = (const float*)d_in[1];
    const float* conv_b = (const float*)d_in[2];
    const float* bn_sc  = (const float*)d_in[3];
    const float* bn_bi  = (const float*)d_in[4];
    const float* bn_mu  = (const float*)d_in[5];
    const float* bn_var = (const float*)d_in[6];
    float* out = (float*)d_out;

    wprep_kernel<<<(COUT * KDIM + 255) / 256, 256>>>(conv_w, conv_b, bn_sc, bn_bi, bn_mu, bn_var);
    shift_split_kernel<<<BATCH * CIN, 256>>>(x);
    dim3 grid((PIX + BNT - 1) / BNT, COUT / BM, BATCH);   // (25, 3, 16)
    gemm_kernel<<<grid, 256>>>(out);
}

// round 9
// speedup vs baseline: 1.3057x; 1.3057x over previous
#include <cuda_runtime.h>
#include <cuda_bf16.h>
#include <cstdint>

// ---------------- problem constants ----------------
#define BATCH 16
#define CIN   384
#define HH    56
#define WW    56
#define PIX   3136
#define COUT  384
#define KDIM  768              // 2*CIN
#define BN_EPS 1e-5f

// ---------------- scratch (device globals; no allocation allowed) ----------------
__device__ __nv_bfloat16 g_XH[(size_t)BATCH * KDIM * PIX];   // 77 MB  [b][k][p] hi
__device__ __nv_bfloat16 g_XL[(size_t)BATCH * KDIM * PIX];   // 77 MB  [b][k][p] lo
__device__ __nv_bfloat16 g_WH[COUT * KDIM];
__device__ __nv_bfloat16 g_WL[COUT * KDIM];
__device__ float         g_TB[COUT];

// ---------------- helpers ----------------
__device__ __forceinline__ uint32_t smem_u32(const void* p) {
    uint32_t a;
    asm("{ .reg .u64 t; cvta.to.shared.u64 t, %1; cvt.u32.u64 %0, t; }" : "=r"(a) : "l"(p));
    return a;
}
__device__ __forceinline__ void cpa16(uint32_t dst, const void* src) {
    asm volatile("cp.async.cg.shared.global [%0], [%1], 16;" :: "r"(dst), "l"(src));
}
__device__ __forceinline__ void cpa16z(uint32_t dst, const void* src, bool ok) {
    int sz = ok ? 16 : 0;
    asm volatile("cp.async.cg.shared.global [%0], [%1], 16, %2;" :: "r"(dst), "l"(src), "r"(sz));
}
#define CP_COMMIT() asm volatile("cp.async.commit_group;" ::: "memory")

__device__ __forceinline__ void ldsm4(uint32_t* d, uint32_t a) {
    asm volatile("ldmatrix.sync.aligned.m8n8.x4.shared.b16 {%0,%1,%2,%3}, [%4];"
        : "=r"(d[0]), "=r"(d[1]), "=r"(d[2]), "=r"(d[3]) : "r"(a));
}
__device__ __forceinline__ void ldsm4t(uint32_t* d, uint32_t a) {
    asm volatile("ldmatrix.sync.aligned.m8n8.x4.trans.shared.b16 {%0,%1,%2,%3}, [%4];"
        : "=r"(d[0]), "=r"(d[1]), "=r"(d[2]), "=r"(d[3]) : "r"(a));
}
__device__ __forceinline__ void mma16816(float* c, const uint32_t* a, const uint32_t* b) {
    asm volatile(
        "mma.sync.aligned.m16n8k16.row.col.f32.bf16.bf16.f32 "
        "{%0,%1,%2,%3}, {%4,%5,%6,%7}, {%8,%9}, {%0,%1,%2,%3};\n"
        : "+f"(c[0]), "+f"(c[1]), "+f"(c[2]), "+f"(c[3])
        : "r"(a[0]), "r"(a[1]), "r"(a[2]), "r"(a[3]), "r"(b[0]), "r"(b[1]));
}
__device__ __forceinline__ float gelu_exact(float v) {
    return 0.5f * v * (1.0f + erff(v * 0.7071067811865476f));
}

// ---------------- kernel 1: weight prep (fold BN, split bf16) ----------------
__global__ void wprep_kernel(const float* __restrict__ w, const float* __restrict__ cb,
                             const float* __restrict__ sc, const float* __restrict__ bi,
                             const float* __restrict__ mu, const float* __restrict__ var) {
    int i = blockIdx.x * 256 + threadIdx.x;
    if (i < COUT * KDIM) {
        int o = i / KDIM;
        float s = sc[o] * rsqrtf(var[o] + BN_EPS);
        float wv = w[i] * s;
        __nv_bfloat16 h = __float2bfloat16(wv);
        g_WH[i] = h;
        g_WL[i] = __float2bfloat16(wv - __bfloat162float(h));
    }
    if (i < COUT) {
        float s = sc[i] * rsqrtf(var[i] + BN_EPS);
        g_TB[i] = (cb[i] - mu[i]) * s + bi[i];
    }
}

// ---------------- kernel 2: shift-max + bf16 hi/lo split writer ----------------
__global__ __launch_bounds__(256) void shift_split_kernel(const float* __restrict__ x) {
    const int bc = blockIdx.x;           // b*CIN + c
    const int c  = bc % CIN;
    const int b  = bc / CIN;
    __shared__ float pl[PIX];
    const float* src = x + (size_t)bc * PIX;
    for (int i = threadIdx.x; i < PIX; i += 256) pl[i] = src[i];
    __syncthreads();

    const size_t baseX = ((size_t)b * KDIM + c)       * PIX;
    const size_t baseJ = ((size_t)b * KDIM + CIN + c) * PIX;

    for (int i = threadIdx.x; i < PIX; i += 256) {
        int h = i / WW, w = i % WW;
        float v = pl[i];
        float m = 0.0f;
        const int shifts[5] = {1, 3, 7, 15, 31};
        #pragma unroll
        for (int j = 0; j < 5; j++) {
            int s = shifts[j];
            int hm = h - s; if (hm < 0)   hm += HH;
            int hp = h + s; if (hp >= HH) hp -= HH;
            m = fmaxf(m, v - pl[hm * WW + w]);
            m = fmaxf(m, v - pl[hp * WW + w]);
            int wm = w - s; if (wm < 0)   wm += WW;
            int wp = w + s; if (wp >= WW) wp -= WW;
            m = fmaxf(m, v - pl[h * WW + wm]);
            m = fmaxf(m, v - pl[h * WW + wp]);
        }
        __nv_bfloat16 xh = __float2bfloat16(v);
        g_XH[baseX + i] = xh;
        g_XL[baseX + i] = __float2bfloat16(v - __bfloat162float(xh));
        __nv_bfloat16 jh = __float2bfloat16(m);
        g_XH[baseJ + i] = jh;
        g_XL[baseJ + i] = __float2bfloat16(m - __bfloat162float(jh));
    }
}

// ---------------- kernel 3: fused 3-term GEMM (cp.async + ldmatrix) + bias + GELU ----------------
// CTA tile: 128 cout x 128 pix, BK=32, fused terms WH*XH + WL*XH + WH*XL.
// smem stage: WH[128x32 pad40] WL XH[32x128 pad136] XL = 37888 B, double buffered.
#define OFF_WH 0
#define OFF_WL 10240
#define OFF_XH 20480
#define OFF_XL 29184
#define STAGE  37888
#define SM_TOTAL (2 * STAGE)   // 75776

extern __shared__ char g_sm[];

__device__ __forceinline__ void load_stage(uint32_t sb, int tid, int b, int o0, int p0,
                                           int kk, int buf) {
    uint32_t base = sb + buf * STAGE;
    const int k0 = kk * 32;
    #pragma unroll
    for (int j = 0; j < 8; j++) {
        int flat = tid + j * 256;
        if (flat < 1024) {
            // weights: 2 mats x 128 rows x 4 segs
            int mat = flat >> 9, u = flat & 511;
            int r = u >> 2, sg = u & 3;
            const __nv_bfloat16* src = (mat ? g_WL : g_WH) + (size_t)(o0 + r) * KDIM + k0 + sg * 8;
            cpa16(base + (mat ? OFF_WL : OFF_WH) + r * 80 + sg * 16, src);
        } else {
            // activations: 2 mats x 32 k-rows x 16 segs
            int u = flat - 1024;
            int mat = u >> 9; u &= 511;
            int k = u >> 4, sg = u & 15;
            int p = p0 + sg * 8;
            bool ok = (p < PIX);
            const __nv_bfloat16* src = (mat ? g_XL : g_XH)
                + ((size_t)b * KDIM + k0 + k) * PIX + (ok ? p : 0);
            cpa16z(base + (mat ? OFF_XL : OFF_XH) + k * 272 + sg * 16, src, ok);
        }
    }
}

__device__ __forceinline__ void compute_stage(uint32_t base, int lane, int wm, int wn,
                                              float acc[4][4][4]) {
    const int g = lane >> 3, r = lane & 7;
    const int rowoff = (g & 1) * 8 + r;     // row within 16-row group
    const int coloff = (g >> 1) * 8;        // col half
    #pragma unroll
    for (int h = 0; h < 2; h++) {
        const int ks = h * 16;
        uint32_t awh[4][4], awl[4][4], bxh[4][2], bxl[4][2];
        #pragma unroll
        for (int mf = 0; mf < 4; mf++) {
            uint32_t off = (uint32_t)((wm * 64 + mf * 16 + rowoff) * 80 + (ks + coloff) * 2);
            ldsm4(awh[mf], base + OFF_WH + off);
            ldsm4(awl[mf], base + OFF_WL + off);
        }
        #pragma unroll
        for (int np = 0; np < 2; np++) {
            uint32_t boff = (uint32_t)((ks + rowoff) * 272 + (wn * 32 + np * 16 + coloff) * 2);
            uint32_t t[4];
            ldsm4t(t, base + OFF_XH + boff);
            bxh[np * 2][0] = t[0]; bxh[np * 2][1] = t[1];
            bxh[np * 2 + 1][0] = t[2]; bxh[np * 2 + 1][1] = t[3];
            ldsm4t(t, base + OFF_XL + boff);
            bxl[np * 2][0] = t[0]; bxl[np * 2][1] = t[1];
            bxl[np * 2 + 1][0] = t[2]; bxl[np * 2 + 1][1] = t[3];
        }
        #pragma unroll
        for (int mf = 0; mf < 4; mf++)
            #pragma unroll
            for (int nf = 0; nf < 4; nf++) {
                mma16816(acc[mf][nf], awh[mf], bxh[nf]);
                mma16816(acc[mf][nf], awl[mf], bxh[nf]);
                mma16816(acc[mf][nf], awh[mf], bxl[nf]);
            }
    }
}

__global__ __launch_bounds__(256, 1) void gemm_kernel(float* __restrict__ out) {
    const int pt = blockIdx.x;    // pixel tile (25)
    const int mt = blockIdx.y;    // cout tile (3)
    const int b  = blockIdx.z;    // batch (16)
    const int p0 = pt * 128;
    const int o0 = mt * 128;
    const int tid  = threadIdx.x;
    const int lane = tid & 31;
    const int warp = tid >> 5;
    const int wm = warp >> 2;     // 0..1 -> m offset *64
    const int wn = warp & 3;      // 0..3 -> n offset *32
    uint32_t sb = smem_u32(g_sm);

    float acc[4][4][4];
    #pragma unroll
    for (int i = 0; i < 4; i++)
        #pragma unroll
        for (int j = 0; j < 4; j++)
            #pragma unroll
            for (int k = 0; k < 4; k++) acc[i][j][k] = 0.0f;

    load_stage(sb, tid, b, o0, p0, 0, 0);
    CP_COMMIT();

    #pragma unroll 1
    for (int kk = 0; kk < KDIM / 32; kk++) {
        if (kk + 1 < KDIM / 32) {
            load_stage(sb, tid, b, o0, p0, kk + 1, (kk + 1) & 1);
            CP_COMMIT();
            asm volatile("cp.async.wait_group 1;" ::: "memory");
        } else {
            asm volatile("cp.async.wait_group 0;" ::: "memory");
        }
        __syncthreads();
        compute_stage(sb + (kk & 1) * STAGE, lane, wm, wn, acc);
        __syncthreads();
    }

    // epilogue: bias (BN folded) + exact GELU, write [b, o, p]
    float* outb = out + (size_t)b * COUT * PIX;
    #pragma unroll
    for (int mf = 0; mf < 4; mf++) {
        int r0 = o0 + wm * 64 + mf * 16 + (lane >> 2);
        float tb0 = g_TB[r0];
        float tb1 = g_TB[r0 + 8];
        #pragma unroll
        for (int nf = 0; nf < 4; nf++) {
            int p = p0 + wn * 32 + nf * 8 + (lane & 3) * 2;
            if (p < PIX) {
                float* o_lo = outb + (size_t)r0 * PIX + p;
                float* o_hi = outb + (size_t)(r0 + 8) * PIX + p;
                o_lo[0] = gelu_exact(acc[mf][nf][0] + tb0);
                o_lo[1] = gelu_exact(acc[mf][nf][1] + tb0);
                o_hi[0] = gelu_exact(acc[mf][nf][2] + tb1);
                o_hi[1] = gelu_exact(acc[mf][nf][3] + tb1);
            }
        }
    }
}

// ---------------- launch ----------------
extern "C" void kernel_launch(void* const* d_in, const int* in_sizes, int n_in,
                              void* d_out, int out_size) {
    const float* x      = (const float*)d_in[0];
    const float* conv_w = (const float*)d_in[1];
    const float* conv_b = (const float*)d_in[2];
    const float* bn_sc  = (const float*)d_in[3];
    const float* bn_bi  = (const float*)d_in[4];
    const float* bn_mu  = (const float*)d_in[5];
    const float* bn_var = (const float*)d_in[6];
    float* out = (float*)d_out;

    cudaFuncSetAttribute(gemm_kernel, cudaFuncAttributeMaxDynamicSharedMemorySize, SM_TOTAL);

    wprep_kernel<<<(COUT * KDIM + 255) / 256, 256>>>(conv_w, conv_b, bn_sc, bn_bi, bn_mu, bn_var);
    shift_split_kernel<<<BATCH * CIN, 256>>>(x);
    dim3 grid(25, 3, BATCH);
    gemm_kernel<<<grid, 256, SM_TOTAL>>>(out);
}

// round 11
// speedup vs baseline: 2.5815x; 1.9770x over previous
#include <cuda_runtime.h>
#include <cuda_fp16.h>
#include <cstdint>

// ---------------- problem constants ----------------
#define BATCH 16
#define CIN   384
#define HH    56
#define WW    56
#define PIX   3136
#define COUT  384
#define KDIM  768              // 2*CIN
#define BN_EPS 1e-5f

// ---------------- scratch (device globals; no allocation allowed) ----------------
__device__ __half g_X[(size_t)BATCH * KDIM * PIX];   // 77 MB  [b][k][p] fp16 (x | x_j)
__device__ __half g_W[COUT * KDIM];                  // BN-folded weights, fp16
__device__ float  g_TB[COUT];                        // BN-folded bias

// ---------------- helpers ----------------
__device__ __forceinline__ uint32_t smem_u32(const void* p) {
    uint32_t a;
    asm("{ .reg .u64 t; cvta.to.shared.u64 t, %1; cvt.u32.u64 %0, t; }" : "=r"(a) : "l"(p));
    return a;
}
__device__ __forceinline__ void cpa16(uint32_t dst, const void* src) {
    asm volatile("cp.async.cg.shared.global [%0], [%1], 16;" :: "r"(dst), "l"(src));
}
__device__ __forceinline__ void cpa16z(uint32_t dst, const void* src, bool ok) {
    int sz = ok ? 16 : 0;
    asm volatile("cp.async.cg.shared.global [%0], [%1], 16, %2;" :: "r"(dst), "l"(src), "r"(sz));
}
#define CP_COMMIT() asm volatile("cp.async.commit_group;" ::: "memory")

__device__ __forceinline__ void ldsm4(uint32_t* d, uint32_t a) {
    asm volatile("ldmatrix.sync.aligned.m8n8.x4.shared.b16 {%0,%1,%2,%3}, [%4];"
        : "=r"(d[0]), "=r"(d[1]), "=r"(d[2]), "=r"(d[3]) : "r"(a));
}
__device__ __forceinline__ void ldsm4t(uint32_t* d, uint32_t a) {
    asm volatile("ldmatrix.sync.aligned.m8n8.x4.trans.shared.b16 {%0,%1,%2,%3}, [%4];"
        : "=r"(d[0]), "=r"(d[1]), "=r"(d[2]), "=r"(d[3]) : "r"(a));
}
__device__ __forceinline__ void mma16816(float* c, const uint32_t* a, const uint32_t* b) {
    asm volatile(
        "mma.sync.aligned.m16n8k16.row.col.f32.f16.f16.f32 "
        "{%0,%1,%2,%3}, {%4,%5,%6,%7}, {%8,%9}, {%0,%1,%2,%3};\n"
        : "+f"(c[0]), "+f"(c[1]), "+f"(c[2]), "+f"(c[3])
        : "r"(a[0]), "r"(a[1]), "r"(a[2]), "r"(a[3]), "r"(b[0]), "r"(b[1]));
}
__device__ __forceinline__ float gelu_exact(float v) {
    return 0.5f * v * (1.0f + erff(v * 0.7071067811865476f));
}

// ---------------- kernel 1: weight prep (fold BN, fp16) ----------------
__global__ void wprep_kernel(const float* __restrict__ w, const float* __restrict__ cb,
                             const float* __restrict__ sc, const float* __restrict__ bi,
                             const float* __restrict__ mu, const float* __restrict__ var) {
    int i = blockIdx.x * 256 + threadIdx.x;
    if (i < COUT * KDIM) {
        int o = i / KDIM;
        float s = sc[o] * rsqrtf(var[o] + BN_EPS);
        g_W[i] = __float2half(w[i] * s);
    }
    if (i < COUT) {
        float s = sc[i] * rsqrtf(var[i] + BN_EPS);
        g_TB[i] = (cb[i] - mu[i]) * s + bi[i];
    }
}

// ---------------- kernel 2: shift-max + fp16 writer ----------------
__global__ __launch_bounds__(256) void shift_split_kernel(const float* __restrict__ x) {
    const int bc = blockIdx.x;           // b*CIN + c
    const int c  = bc % CIN;
    const int b  = bc / CIN;
    __shared__ float pl[PIX];
    const float* src = x + (size_t)bc * PIX;
    for (int i = threadIdx.x; i < PIX; i += 256) pl[i] = src[i];
    __syncthreads();

    __half* dstX = g_X + ((size_t)b * KDIM + c)       * PIX;
    __half* dstJ = g_X + ((size_t)b * KDIM + CIN + c) * PIX;

    for (int i = threadIdx.x; i < PIX; i += 256) {
        int h = i / WW, w = i % WW;
        float v = pl[i];
        float m = 0.0f;
        const int shifts[5] = {1, 3, 7, 15, 31};
        #pragma unroll
        for (int j = 0; j < 5; j++) {
            int s = shifts[j];
            int hm = h - s; if (hm < 0)   hm += HH;
            int hp = h + s; if (hp >= HH) hp -= HH;
            m = fmaxf(m, v - pl[hm * WW + w]);
            m = fmaxf(m, v - pl[hp * WW + w]);
            int wm = w - s; if (wm < 0)   wm += WW;
            int wp = w + s; if (wp >= WW) wp -= WW;
            m = fmaxf(m, v - pl[h * WW + wm]);
            m = fmaxf(m, v - pl[h * WW + wp]);
        }
        dstX[i] = __float2half(v);
        dstJ[i] = __float2half(m);
    }
}

// ---------------- kernel 3: fp16 GEMM (cp.async 4-stage + ldmatrix) + bias + GELU ----------------
// CTA tile: 128 cout x 128 pix, BK=32.
// Stage: A 128x32 fp16 (row stride 80B) = 10240 B, B 32x128 fp16 (row stride 272B) = 8704 B.
#define OFF_A  0
#define OFF_B  10240
#define STAGE  18944
#define NSTAGE 4
#define SM_TOTAL (NSTAGE * STAGE)   // 75776 -> 2 CTAs/SM

extern __shared__ char g_sm[];

__device__ __forceinline__ void load_stage(uint32_t base, int tid, int b, int o0, int p0, int kk) {
    const int k0 = kk * 32;
    #pragma unroll
    for (int j = 0; j < 4; j++) {
        int flat = tid + j * 256;
        if (flat < 512) {
            // weights: 128 rows x 4 segs of 16B
            int r = flat >> 2, sg = flat & 3;
            cpa16(base + OFF_A + r * 80 + sg * 16,
                  g_W + (size_t)(o0 + r) * KDIM + k0 + sg * 8);
        } else {
            // activations: 32 k-rows x 16 segs of 16B
            int u = flat - 512;
            int k = u >> 4, sg = u & 15;
            int p = p0 + sg * 8;
            bool ok = (p < PIX);
            cpa16z(base + OFF_B + k * 272 + sg * 16,
                   g_X + ((size_t)b * KDIM + k0 + k) * PIX + (ok ? p : 0), ok);
        }
    }
}

__device__ __forceinline__ void compute_stage(uint32_t base, int lane, int wm, int wn,
                                              float acc[4][4][4]) {
    const int g = lane >> 3, r = lane & 7;
    const int rowoff = (g & 1) * 8 + r;     // row within 16-row group
    const int coloff = (g >> 1) * 8;        // col half
    #pragma unroll
    for (int h = 0; h < 2; h++) {
        const int ks = h * 16;
        uint32_t a[4][4], bb[4][2];
        #pragma unroll
        for (int mf = 0; mf < 4; mf++)
            ldsm4(a[mf], base + OFF_A + (uint32_t)((wm * 64 + mf * 16 + rowoff) * 80 + (ks + coloff) * 2));
        #pragma unroll
        for (int np = 0; np < 2; np++) {
            uint32_t t[4];
            ldsm4t(t, base + OFF_B + (uint32_t)((ks + rowoff) * 272 + (wn * 32 + np * 16 + coloff) * 2));
            bb[np * 2][0]     = t[0]; bb[np * 2][1]     = t[1];
            bb[np * 2 + 1][0] = t[2]; bb[np * 2 + 1][1] = t[3];
        }
        #pragma unroll
        for (int mf = 0; mf < 4; mf++)
            #pragma unroll
            for (int nf = 0; nf < 4; nf++)
                mma16816(acc[mf][nf], a[mf], bb[nf]);
    }
}

__global__ __launch_bounds__(256, 2) void gemm_kernel(float* __restrict__ out) {
    const int pt = blockIdx.x;    // pixel tile (25)
    const int mt = blockIdx.y;    // cout tile (3)
    const int b  = blockIdx.z;    // batch (16)
    const int p0 = pt * 128;
    const int o0 = mt * 128;
    const int tid  = threadIdx.x;
    const int lane = tid & 31;
    const int warp = tid >> 5;
    const int wm = warp >> 2;     // 0..1 -> m offset *64
    const int wn = warp & 3;      // 0..3 -> n offset *32
    uint32_t sb = smem_u32(g_sm);

    float acc[4][4][4];
    #pragma unroll
    for (int i = 0; i < 4; i++)
        #pragma unroll
        for (int j = 0; j < 4; j++)
            #pragma unroll
            for (int k = 0; k < 4; k++) acc[i][j][k] = 0.0f;

    // prologue: 3 stages in flight
    #pragma unroll
    for (int s = 0; s < NSTAGE - 1; s++) {
        load_stage(sb + s * STAGE, tid, b, o0, p0, s);
        CP_COMMIT();
    }

    #pragma unroll 1
    for (int kk = 0; kk < KDIM / 32; kk++) {
        if (kk <= KDIM / 32 - 3)      asm volatile("cp.async.wait_group 2;" ::: "memory");
        else if (kk == KDIM / 32 - 2) asm volatile("cp.async.wait_group 1;" ::: "memory");
        else                          asm volatile("cp.async.wait_group 0;" ::: "memory");
        __syncthreads();
        int ii = kk + NSTAGE - 1;
        if (ii < KDIM / 32) {
            load_stage(sb + (ii & (NSTAGE - 1)) * STAGE, tid, b, o0, p0, ii);
            CP_COMMIT();
        }
        compute_stage(sb + (kk & (NSTAGE - 1)) * STAGE, lane, wm, wn, acc);
    }

    // epilogue: bias (BN folded) + exact GELU, write [b, o, p]
    float* outb = out + (size_t)b * COUT * PIX;
    #pragma unroll
    for (int mf = 0; mf < 4; mf++) {
        int r0 = o0 + wm * 64 + mf * 16 + (lane >> 2);
        float tb0 = g_TB[r0];
        float tb1 = g_TB[r0 + 8];
        #pragma unroll
        for (int nf = 0; nf < 4; nf++) {
            int p = p0 + wn * 32 + nf * 8 + (lane & 3) * 2;
            if (p < PIX) {
                float* o_lo = outb + (size_t)r0 * PIX + p;
                float* o_hi = outb + (size_t)(r0 + 8) * PIX + p;
                o_lo[0] = gelu_exact(acc[mf][nf][0] + tb0);
                o_lo[1] = gelu_exact(acc[mf][nf][1] + tb0);
                o_hi[0] = gelu_exact(acc[mf][nf][2] + tb1);
                o_hi[1] = gelu_exact(acc[mf][nf][3] + tb1);
            }
        }
    }
}

// ---------------- launch ----------------
extern "C" void kernel_launch(void* const* d_in, const int* in_sizes, int n_in,
                              void* d_out, int out_size) {
    const float* x      = (const float*)d_in[0];
    const float* conv_w = (const float*)d_in[1];
    const float* conv_b = (const float*)d_in[2];
    const float* bn_sc  = (const float*)d_in[3];
    const float* bn_bi  = (const float*)d_in[4];
    const float* bn_mu  = (const float*)d_in[5];
    const float* bn_var = (const float*)d_in[6];
    float* out = (float*)d_out;

    cudaFuncSetAttribute(gemm_kernel, cudaFuncAttributeMaxDynamicSharedMemorySize, SM_TOTAL);

    wprep_kernel<<<(COUT * KDIM + 255) / 256, 256>>>(conv_w, conv_b, bn_sc, bn_bi, bn_mu, bn_var);
    shift_split_kernel<<<BATCH * CIN, 256>>>(x);
    dim3 grid(25, 3, BATCH);
    gemm_kernel<<<grid, 256, SM_TOTAL>>>(out);
}